// round 7
// baseline (speedup 1.0000x reference)
#include <cuda_runtime.h>

#define EPS_F 1e-16f
#define NEG_SLOPE 0.2f

static const int MAXN = 50048;
static const int MAXE = 850048;
static const int NBMAX = 64;

// scratch (device globals — no allocation allowed)
__device__ int   g_deg[MAXN];
__device__ int   g_off[MAXN + 1];
__device__ int   g_cur[MAXN];
__device__ int   g_csr_src[MAXE];
__device__ int   g_csr_eid[MAXE];
__device__ float g_ew[MAXE];
__device__ int   g_bsum[NBMAX];
__device__ __align__(16) float g_h[(size_t)MAXN * 64];   // layer1 h
__device__ __align__(16) float g_h2[(size_t)MAXN * 64];  // layer2 h
__device__ __align__(16) float g_h3[(size_t)MAXN * 32];  // layer3 h
__device__ float g_asA[MAXN];
__device__ float g_adA[MAXN];
__device__ float g_asB[MAXN];
__device__ float g_adB[MAXN];
__device__ int   g_is64;

// ---------------------------------------------------------------------------
// init: zero degree array; block 0 also detects edge dtype (int64 vs int32).
// ---------------------------------------------------------------------------
__global__ void init_kernel(const int* __restrict__ ei32, int n) {
    int i = blockIdx.x * blockDim.x + threadIdx.x;
    if (i < n) g_deg[i] = 0;
    if (blockIdx.x == 0 && threadIdx.x == 0) {
        int all_zero = 1;
        #pragma unroll
        for (int k = 0; k < 64; k++)
            if (ei32[2 * k + 1] != 0) { all_zero = 0; break; }
        g_is64 = all_zero;
    }
}

// ---------------------------------------------------------------------------
__device__ __forceinline__ void load_edge(const int* __restrict__ ei32,
                                          int e, int E, int n, int& s, int& d) {
    if (e < E) {
        if (g_is64) {
            const long long* ei = (const long long*)ei32;
            s = (int)ei[e]; d = (int)ei[E + e];
        } else {
            s = ei32[e]; d = ei32[E + e];
        }
    } else {
        s = d = e - E;   // self loop
    }
    s = min(max(s, 0), n - 1);
    d = min(max(d, 0), n - 1);
}

// Count per-dst degree; emit stacked (src,dst) as float at head of d_out.
__global__ void build_edges(const int* __restrict__ ei32, int E, int Ep, int n,
                            float* __restrict__ outIdx) {
    int e = blockIdx.x * blockDim.x + threadIdx.x;
    if (e >= Ep) return;
    int s, d;
    load_edge(ei32, e, E, n, s, d);
    atomicAdd(&g_deg[d], 1);
    outIdx[e]      = (float)s;
    outIdx[Ep + e] = (float)d;
}

// ---------------------------------------------------------------------------
// Scan: phase1 = per-1024-chunk sums; phase3 = per-chunk scan + self base.
// ---------------------------------------------------------------------------
__global__ void scan_phase1(int n) {
    __shared__ int warpsum[32];
    int tid = threadIdx.x, lane = tid & 31, wid = tid >> 5;
    int i = blockIdx.x * 1024 + tid;
    int v = (i < n) ? g_deg[i] : 0;
    #pragma unroll
    for (int off = 16; off > 0; off >>= 1)
        v += __shfl_down_sync(0xffffffffu, v, off);
    if (lane == 0) warpsum[wid] = v;
    __syncthreads();
    if (wid == 0) {
        int t = warpsum[lane];
        #pragma unroll
        for (int off = 16; off > 0; off >>= 1)
            t += __shfl_down_sync(0xffffffffu, t, off);
        if (lane == 0) g_bsum[blockIdx.x] = t;
    }
}

__global__ void scan_phase3(int n) {
    __shared__ int warpsum[32];
    __shared__ int s_base;
    int tid = threadIdx.x, lane = tid & 31, wid = tid >> 5;
    if (tid == 0) {
        int b = 0;
        for (int i = 0; i < blockIdx.x; i++) b += g_bsum[i];
        s_base = b;
    }
    int i = blockIdx.x * 1024 + tid;
    int v = (i < n) ? g_deg[i] : 0;
    int incl = v;
    #pragma unroll
    for (int off = 1; off < 32; off <<= 1) {
        int t = __shfl_up_sync(0xffffffffu, incl, off);
        if (lane >= off) incl += t;
    }
    if (lane == 31) warpsum[wid] = incl;
    __syncthreads();
    if (wid == 0) {
        int ws = warpsum[lane];
        int wincl = ws;
        #pragma unroll
        for (int off = 1; off < 32; off <<= 1) {
            int t = __shfl_up_sync(0xffffffffu, wincl, off);
            if (lane >= off) wincl += t;
        }
        warpsum[lane] = wincl - ws;
    }
    __syncthreads();
    int excl = incl - v + warpsum[wid] + s_base;
    if (i < n) {
        g_off[i] = excl;
        g_cur[i] = excl;
        if (i == n - 1) g_off[n] = excl + v;
    }
}

__global__ void place_edges(const int* __restrict__ ei32, int E, int Ep, int n) {
    int e = blockIdx.x * blockDim.x + threadIdx.x;
    if (e >= Ep) return;
    int s, d;
    load_edge(ei32, e, E, n, s, d);
    int pos = atomicAdd(&g_cur[d], 1);
    g_csr_src[pos] = s;
    g_csr_eid[pos] = e;
}

// ---------------------------------------------------------------------------
// GEMM1 only: h = x @ W1^T ; g_asA = h.a_src ; g_adA = h.a_dst.
// 4 warps/block, 4 rows/warp, float4 smem loads (FMA-dense).
// ---------------------------------------------------------------------------
__global__ __launch_bounds__(128)
void gat_gemm1(const float* __restrict__ xin, const float* __restrict__ W,
               const float* __restrict__ av, const float* __restrict__ dv,
               int n) {
    constexpr int FIN = 128, FOUT = 64, P = FIN + 4;
    __shared__ float sW[FOUT * P];
    __shared__ __align__(16) float srow[4][4][FIN];
    __shared__ float sA[FOUT];
    __shared__ float sD[FOUT];

    int tid = threadIdx.x;
    for (int i = tid; i < FOUT * FIN; i += 128) {
        int j = i / FIN, k = i % FIN;
        sW[j * P + k] = W[i];
    }
    if (tid < FOUT) { sA[tid] = av[tid]; sD[tid] = dv[tid]; }
    __syncthreads();

    int w = tid >> 5, lane = tid & 31;
    int j0 = lane, j1 = 32 + lane;

    for (int row0 = (blockIdx.x * 4 + w) * 4; row0 < n; row0 += gridDim.x * 16) {
        int nr = min(4, n - row0);
        for (int r = 0; r < nr; r++) {
            const float4* rp = (const float4*)(xin + (size_t)(row0 + r) * FIN);
            ((float4*)srow[w][r])[lane] = rp[lane];
        }
        __syncwarp();

        float acc[4][2];
        #pragma unroll
        for (int r = 0; r < 4; r++) { acc[r][0] = 0.f; acc[r][1] = 0.f; }

        #pragma unroll
        for (int kq = 0; kq < FIN / 4; kq++) {
            float4 w0 = *(const float4*)&sW[j0 * P + kq * 4];
            float4 w1 = *(const float4*)&sW[j1 * P + kq * 4];
            #pragma unroll
            for (int r = 0; r < 4; r++) {
                float4 rv = ((const float4*)srow[w][r])[kq];
                acc[r][0] = fmaf(rv.x, w0.x, acc[r][0]);
                acc[r][0] = fmaf(rv.y, w0.y, acc[r][0]);
                acc[r][0] = fmaf(rv.z, w0.z, acc[r][0]);
                acc[r][0] = fmaf(rv.w, w0.w, acc[r][0]);
                acc[r][1] = fmaf(rv.x, w1.x, acc[r][1]);
                acc[r][1] = fmaf(rv.y, w1.y, acc[r][1]);
                acc[r][1] = fmaf(rv.z, w1.z, acc[r][1]);
                acc[r][1] = fmaf(rv.w, w1.w, acc[r][1]);
            }
        }

        for (int r = 0; r < nr; r++) {
            int row = row0 + r;
            g_h[(size_t)row * FOUT + j0] = acc[r][0];
            g_h[(size_t)row * FOUT + j1] = acc[r][1];
            float pa = acc[r][0] * sA[j0] + acc[r][1] * sA[j1];
            float pd = acc[r][0] * sD[j0] + acc[r][1] * sD[j1];
            #pragma unroll
            for (int o = 16; o > 0; o >>= 1) {
                pa += __shfl_down_sync(0xffffffffu, pa, o);
                pd += __shfl_down_sync(0xffffffffu, pd, o);
            }
            if (lane == 0) { g_asA[row] = pa; g_adA[row] = pd; }
        }
        __syncwarp();
    }
}

// ---------------------------------------------------------------------------
// Fused layer kernel: warp per dst node d.
//  MODE 0: gather layer1 (g_h,64, as/adA) -> v=relu(acc/s+b1); alpha out;
//          gemm v@W2^T (64->64) -> g_h2, as/adB.
//  MODE 1: gather layer2 (g_h2,64, as/adB) -> v=relu(acc/s+b2);
//          gemm v@W3^T (64->32) -> g_h3, as/adA.
//  MODE 2: gather layer3 (g_h3,32, as/adA) -> outO = acc/s + b3.
// ---------------------------------------------------------------------------
template<int MODE>
__global__ __launch_bounds__(256)
void gat_fused(int n, const float* __restrict__ W,
               const float* __restrict__ av, const float* __restrict__ dv,
               const float* __restrict__ bias,
               float* __restrict__ outAlpha, float* __restrict__ outO) {
    constexpr int FING  = (MODE == 2) ? 32 : 64;     // gather width
    constexpr int FOUTG = (MODE == 0) ? 64 : 32;     // gemm out width
    constexpr int GSZ = FING / 4;
    constexpr int NG  = 32 / GSZ;
    constexpr int P = 64 + 4;

    __shared__ float sW[(MODE == 2) ? 1 : FOUTG * P];
    __shared__ float sA[(MODE == 2) ? 1 : FOUTG];
    __shared__ float sD[(MODE == 2) ? 1 : FOUTG];
    __shared__ float sB[FING];
    __shared__ __align__(16) float srow[8][64];

    int tid = threadIdx.x;
    if (MODE != 2) {
        for (int i = tid; i < FOUTG * 64; i += 256) {
            int j = i >> 6, k = i & 63;
            sW[j * P + k] = W[i];
        }
        if (tid < FOUTG) { sA[tid] = av[tid]; sD[tid] = dv[tid]; }
    }
    if (tid < FING) sB[tid] = bias[tid];
    __syncthreads();

    int wg = (blockIdx.x * blockDim.x + tid) >> 5;
    int lane = tid & 31;
    int w = tid >> 5;
    if (wg >= n) return;
    int d = wg;
    int beg = g_off[d], end = g_off[d + 1];

    const float* hsrc = (MODE == 0) ? g_h : (MODE == 1 ? g_h2 : g_h3);
    const float* asv  = (MODE == 1) ? g_asB : g_asA;
    float ad = (MODE == 1) ? g_adB[d] : g_adA[d];
    int g = lane / GSZ, fl = lane % GSZ;

    float4 acc = make_float4(0.f, 0.f, 0.f, 0.f);
    float s = 0.f;

    for (int p0 = beg; p0 < end; p0 += 32) {
        int cnt = min(32, end - p0);
        int src_l = 0;
        float w_l = 0.f;
        if (lane < cnt) {
            src_l = g_csr_src[p0 + lane];
            float v = asv[src_l] + ad;
            v = v > 0.f ? v : NEG_SLOPE * v;
            w_l = __expf(v);
            if (MODE == 0) g_ew[p0 + lane] = w_l;
        }
        #pragma unroll 2
        for (int q = 0; q < cnt; q += NG) {
            int idx = q + g;
            float wh  = __shfl_sync(0xffffffffu, w_l, idx & 31);
            int  srch = __shfl_sync(0xffffffffu, src_l, idx & 31);
            float w2 = (idx < cnt) ? wh : 0.f;
            float4 hv = *(const float4*)&hsrc[(size_t)srch * FING + fl * 4];
            acc.x = fmaf(w2, hv.x, acc.x);
            acc.y = fmaf(w2, hv.y, acc.y);
            acc.z = fmaf(w2, hv.z, acc.z);
            acc.w = fmaf(w2, hv.w, acc.w);
            s += w2;
        }
    }
    // combine groups (butterfly -> all lanes hold totals)
    #pragma unroll
    for (int off = GSZ; off < 32; off <<= 1) {
        s     += __shfl_xor_sync(0xffffffffu, s, off);
        acc.x += __shfl_xor_sync(0xffffffffu, acc.x, off);
        acc.y += __shfl_xor_sync(0xffffffffu, acc.y, off);
        acc.z += __shfl_xor_sync(0xffffffffu, acc.z, off);
        acc.w += __shfl_xor_sync(0xffffffffu, acc.w, off);
    }
    float sinv = 1.f / (s + EPS_F);

    float4 o;
    o.x = fmaf(acc.x, sinv, sB[fl * 4 + 0]);
    o.y = fmaf(acc.y, sinv, sB[fl * 4 + 1]);
    o.z = fmaf(acc.z, sinv, sB[fl * 4 + 2]);
    o.w = fmaf(acc.w, sinv, sB[fl * 4 + 3]);

    if (MODE == 2) {
        if (lane < GSZ) *(float4*)&outO[(size_t)d * 32 + fl * 4] = o;
        return;
    }

    // relu -> next-layer input v, staged in per-warp smem row
    o.x = fmaxf(o.x, 0.f); o.y = fmaxf(o.y, 0.f);
    o.z = fmaxf(o.z, 0.f); o.w = fmaxf(o.w, 0.f);
    if (lane < GSZ) *(float4*)&srow[w][fl * 4] = o;
    __syncwarp();

    // in-warp GEMM: lane computes outputs j0 = lane (, j1 = lane+32)
    float a0 = 0.f, a1 = 0.f;
    #pragma unroll
    for (int kq = 0; kq < 16; kq++) {
        float4 rv = ((const float4*)srow[w])[kq];
        float4 w0 = *(const float4*)&sW[lane * P + kq * 4];
        a0 = fmaf(rv.x, w0.x, a0);
        a0 = fmaf(rv.y, w0.y, a0);
        a0 = fmaf(rv.z, w0.z, a0);
        a0 = fmaf(rv.w, w0.w, a0);
        if (FOUTG == 64) {
            float4 w1 = *(const float4*)&sW[(lane + 32) * P + kq * 4];
            a1 = fmaf(rv.x, w1.x, a1);
            a1 = fmaf(rv.y, w1.y, a1);
            a1 = fmaf(rv.z, w1.z, a1);
            a1 = fmaf(rv.w, w1.w, a1);
        }
    }
    float* hdst = (MODE == 0) ? g_h2 : g_h3;
    hdst[(size_t)d * FOUTG + lane] = a0;
    float pa = a0 * sA[lane], pd = a0 * sD[lane];
    if (FOUTG == 64) {
        hdst[(size_t)d * 64 + lane + 32] = a1;
        pa = fmaf(a1, sA[lane + 32], pa);
        pd = fmaf(a1, sD[lane + 32], pd);
    }
    #pragma unroll
    for (int off = 16; off > 0; off >>= 1) {
        pa += __shfl_xor_sync(0xffffffffu, pa, off);
        pd += __shfl_xor_sync(0xffffffffu, pd, off);
    }
    if (lane == 0) {
        if (MODE == 0) { g_asB[d] = pa; g_adB[d] = pd; }
        else           { g_asA[d] = pa; g_adA[d] = pd; }
    }

    // layer-1 alpha output (coalesced read of g_ew written above by this warp)
    if (MODE == 0) {
        for (int p = beg + lane; p < end; p += 32)
            outAlpha[g_csr_eid[p]] = g_ew[p] * sinv;
    }
}

// ---------------------------------------------------------------------------

extern "C" void kernel_launch(void* const* d_in, const int* in_sizes, int n_in,
                              void* d_out, int out_size) {
    const float* x    = (const float*)d_in[0];
    const int*   ei32 = (const int*)d_in[1];
    const float* W1 = (const float*)d_in[2];
    const float* a1s = (const float*)d_in[3];
    const float* a1d = (const float*)d_in[4];
    const float* b1 = (const float*)d_in[5];
    const float* W2 = (const float*)d_in[6];
    const float* a2s = (const float*)d_in[7];
    const float* a2d = (const float*)d_in[8];
    const float* b2 = (const float*)d_in[9];
    const float* W3 = (const float*)d_in[10];
    const float* a3s = (const float*)d_in[11];
    const float* a3d = (const float*)d_in[12];
    const float* b3 = (const float*)d_in[13];

    const int N  = in_sizes[0] / 128;     // 50000
    const int E  = in_sizes[1] / 2;       // 800000
    const int Ep = E + N;                 // with self loops

    float* out      = (float*)d_out;
    float* outAlpha = out + 2 * (size_t)Ep;
    float* outO     = out + 3 * (size_t)Ep;

    const int TB = 256;
    int ebl = (Ep + TB - 1) / TB;
    int nb = (N + 1023) / 1024;
    int gemm_grid = (N + 15) / 16;
    int gath_grid = (N + 7) / 8;

    // one-time side-stream for overlapping GEMM1 with preprocessing
    static cudaStream_t s2 = nullptr;
    static cudaEvent_t evFork = nullptr, evJoin = nullptr;
    if (!s2) {
        cudaStreamCreateWithFlags(&s2, cudaStreamNonBlocking);
        cudaEventCreateWithFlags(&evFork, cudaEventDisableTiming);
        cudaEventCreateWithFlags(&evJoin, cudaEventDisableTiming);
    }

    // fork: GEMM1 runs on s2, independent of edge preprocessing
    cudaEventRecord(evFork, 0);
    cudaStreamWaitEvent(s2, evFork, 0);
    gat_gemm1<<<gemm_grid, 128, 0, s2>>>(x, W1, a1s, a1d, N);
    cudaEventRecord(evJoin, s2);

    // preprocessing chain on main stream
    init_kernel<<<(N + TB - 1) / TB, TB>>>(ei32, N);
    build_edges<<<ebl, TB>>>(ei32, E, Ep, N, out);
    scan_phase1<<<nb, 1024>>>(N);
    scan_phase3<<<nb, 1024>>>(N);
    place_edges<<<ebl, TB>>>(ei32, E, Ep, N);

    // join: fused layer 1 needs both CSR and GEMM1 results
    cudaStreamWaitEvent(0, evJoin, 0);

    // fused layers
    gat_fused<0><<<gath_grid, TB>>>(N, W2, a2s, a2d, b1, outAlpha, nullptr);
    gat_fused<1><<<gath_grid, TB>>>(N, W3, a3s, a3d, b2, nullptr, nullptr);
    gat_fused<2><<<gath_grid, TB>>>(N, nullptr, nullptr, nullptr, b3, nullptr, outO);
}

// round 8
// speedup vs baseline: 1.0835x; 1.0835x over previous
#include <cuda_runtime.h>

#define EPS_F 1e-16f
#define NEG_SLOPE 0.2f

static const int MAXN = 50048;
static const int MAXE = 850048;
static const int NBMAX = 64;

// scratch (device globals — no allocation allowed)
__device__ int   g_deg[MAXN];
__device__ int   g_off[MAXN + 1];
__device__ int   g_cur[MAXN];
__device__ int   g_csr_src[MAXE];
__device__ int   g_bsum[NBMAX];
__device__ int   g_scanDone;
__device__ __align__(16) float g_h[(size_t)MAXN * 64];
__device__ __align__(16) float g_aggA[(size_t)MAXN * 64];
__device__ __align__(16) float g_aggB[(size_t)MAXN * 64];
__device__ float g_asA[MAXN];
__device__ float g_adA[MAXN];
__device__ float g_asB[MAXN];
__device__ float g_adB[MAXN];
__device__ float g_asC[MAXN];
__device__ float g_adC[MAXN];
__device__ float g_sinv[MAXN];
__device__ int   g_is64;

// ---------------------------------------------------------------------------
// init: zero degree array + scan counter; block 0 detects edge dtype.
// ---------------------------------------------------------------------------
__global__ void init_kernel(const int* __restrict__ ei32, int n) {
    int i = blockIdx.x * blockDim.x + threadIdx.x;
    if (i < n) g_deg[i] = 0;
    if (blockIdx.x == 0 && threadIdx.x == 0) {
        g_scanDone = 0;
        int all_zero = 1;
        #pragma unroll
        for (int k = 0; k < 64; k++)
            if (ei32[2 * k + 1] != 0) { all_zero = 0; break; }
        g_is64 = all_zero;
    }
}

// ---------------------------------------------------------------------------
__device__ __forceinline__ void load_edge(const int* __restrict__ ei32,
                                          int e, int E, int n, int& s, int& d) {
    if (e < E) {
        if (g_is64) {
            const long long* ei = (const long long*)ei32;
            s = (int)ei[e]; d = (int)ei[E + e];
        } else {
            s = ei32[e]; d = ei32[E + e];
        }
    } else {
        s = d = e - E;   // self loop
    }
    s = min(max(s, 0), n - 1);
    d = min(max(d, 0), n - 1);
}

// Count per-dst degree; emit stacked (src,dst) as float at head of d_out.
__global__ void build_edges(const int* __restrict__ ei32, int E, int Ep, int n,
                            float* __restrict__ outIdx) {
    int e = blockIdx.x * blockDim.x + threadIdx.x;
    if (e >= Ep) return;
    int s, d;
    load_edge(ei32, e, E, n, s, d);
    atomicAdd(&g_deg[d], 1);
    outIdx[e]      = (float)s;
    outIdx[Ep + e] = (float)d;
}

// ---------------------------------------------------------------------------
// Single-pass scan: each block scans its 1024-chunk, publishes its total,
// spins until all blocks published (grid <= 49 blocks, all resident), then
// adds the prefix of preceding block totals. Writes g_off / g_cur.
// ---------------------------------------------------------------------------
__global__ void scan_single(int n, int nb) {
    __shared__ int warpsum[32];
    __shared__ int s_base;
    int tid = threadIdx.x, lane = tid & 31, wid = tid >> 5;
    int i = blockIdx.x * 1024 + tid;
    int v = (i < n) ? g_deg[i] : 0;

    int incl = v;
    #pragma unroll
    for (int off = 1; off < 32; off <<= 1) {
        int t = __shfl_up_sync(0xffffffffu, incl, off);
        if (lane >= off) incl += t;
    }
    if (lane == 31) warpsum[wid] = incl;
    __syncthreads();
    if (wid == 0) {
        int ws = warpsum[lane];
        int wincl = ws;
        #pragma unroll
        for (int off = 1; off < 32; off <<= 1) {
            int t = __shfl_up_sync(0xffffffffu, wincl, off);
            if (lane >= off) wincl += t;
        }
        warpsum[lane] = wincl - ws;
    }
    __syncthreads();
    incl += warpsum[wid];                       // block-inclusive

    if (tid == 1023) {                          // publish block total
        g_bsum[blockIdx.x] = incl;
        __threadfence();
        atomicAdd(&g_scanDone, 1);
    }
    if (tid == 0) {
        while (atomicAdd(&g_scanDone, 0) < nb) { }
        int b = 0;
        for (int j = 0; j < blockIdx.x; j++)
            b += *(volatile int*)&g_bsum[j];
        s_base = b;
    }
    __syncthreads();

    int excl = incl - v + s_base;
    if (i < n) {
        g_off[i] = excl;
        g_cur[i] = excl;
        if (i == n - 1) g_off[n] = excl + v;
    }
}

__global__ void place_edges(const int* __restrict__ ei32, int E, int Ep, int n) {
    int e = blockIdx.x * blockDim.x + threadIdx.x;
    if (e >= Ep) return;
    int s, d;
    load_edge(ei32, e, E, n, s, d);
    int pos = atomicAdd(&g_cur[d], 1);
    g_csr_src[pos] = s;
}

// ---------------------------------------------------------------------------
// GEMM: h = in @ W^T ; as = h.a_src ; ad = h.a_dst (into buffer ASEL).
// 4 warps/block, 4 rows/warp, float4 smem loads (FMA-dense).
// INSEL: 0 = xin param, 1 = g_aggA, 2 = g_aggB.  ASEL: 0=A, 1=B, 2=C.
// ---------------------------------------------------------------------------
template<int FIN, int FOUT, int INSEL, int ASEL>
__global__ __launch_bounds__(128)
void gat_gemm(const float* __restrict__ xin, const float* __restrict__ W,
              const float* __restrict__ av, const float* __restrict__ dv,
              int n) {
    constexpr int P = FIN + 4;
    __shared__ float sW[FOUT * P];
    __shared__ __align__(16) float srow[4][4][FIN];
    __shared__ float sA[FOUT];
    __shared__ float sD[FOUT];

    int tid = threadIdx.x;
    for (int i = tid; i < FOUT * FIN; i += 128) {
        int j = i / FIN, k = i % FIN;
        sW[j * P + k] = W[i];
    }
    if (tid < FOUT) { sA[tid] = av[tid]; sD[tid] = dv[tid]; }
    __syncthreads();

    const float* in = (INSEL == 0) ? xin : (INSEL == 1 ? g_aggA : g_aggB);
    float* asOut = (ASEL == 0) ? g_asA : (ASEL == 1 ? g_asB : g_asC);
    float* adOut = (ASEL == 0) ? g_adA : (ASEL == 1 ? g_adB : g_adC);
    int w = tid >> 5, lane = tid & 31;
    int j0 = lane, j1 = 32 + lane;

    for (int row0 = (blockIdx.x * 4 + w) * 4; row0 < n; row0 += gridDim.x * 16) {
        int nr = min(4, n - row0);
        for (int r = 0; r < nr; r++) {
            const float4* rp = (const float4*)(in + (size_t)(row0 + r) * FIN);
            if (FIN == 128) ((float4*)srow[w][r])[lane] = rp[lane];
            else if (lane < FIN / 4) ((float4*)srow[w][r])[lane] = rp[lane];
        }
        __syncwarp();

        float acc[4][FOUT / 32];
        #pragma unroll
        for (int r = 0; r < 4; r++)
            #pragma unroll
            for (int c = 0; c < FOUT / 32; c++) acc[r][c] = 0.f;

        #pragma unroll
        for (int kq = 0; kq < FIN / 4; kq++) {
            float4 w0 = *(const float4*)&sW[j0 * P + kq * 4];
            float4 w1;
            if (FOUT > 32) w1 = *(const float4*)&sW[j1 * P + kq * 4];
            #pragma unroll
            for (int r = 0; r < 4; r++) {
                float4 rv = ((const float4*)srow[w][r])[kq];
                acc[r][0] = fmaf(rv.x, w0.x, acc[r][0]);
                acc[r][0] = fmaf(rv.y, w0.y, acc[r][0]);
                acc[r][0] = fmaf(rv.z, w0.z, acc[r][0]);
                acc[r][0] = fmaf(rv.w, w0.w, acc[r][0]);
                if (FOUT > 32) {
                    acc[r][1] = fmaf(rv.x, w1.x, acc[r][1]);
                    acc[r][1] = fmaf(rv.y, w1.y, acc[r][1]);
                    acc[r][1] = fmaf(rv.z, w1.z, acc[r][1]);
                    acc[r][1] = fmaf(rv.w, w1.w, acc[r][1]);
                }
            }
        }

        for (int r = 0; r < nr; r++) {
            int row = row0 + r;
            float pa, pd;
            g_h[(size_t)row * FOUT + j0] = acc[r][0];
            pa = acc[r][0] * sA[j0];
            pd = acc[r][0] * sD[j0];
            if (FOUT > 32) {
                g_h[(size_t)row * FOUT + j1] = acc[r][1];
                pa = fmaf(acc[r][1], sA[j1], pa);
                pd = fmaf(acc[r][1], sD[j1], pd);
            }
            #pragma unroll
            for (int o = 16; o > 0; o >>= 1) {
                pa += __shfl_down_sync(0xffffffffu, pa, o);
                pd += __shfl_down_sync(0xffffffffu, pd, o);
            }
            if (lane == 0) { asOut[row] = pa; adOut[row] = pd; }
        }
        __syncwarp();
    }
}

// ---------------------------------------------------------------------------
// CSR gather: warp per dst node, group-per-edge float4 layout.
// MODE 0 (layer1): as/adA -> out relu(acc/s + b1) -> g_aggA; store g_sinv.
// MODE 1 (layer2): as/adB -> out relu(acc/s + b2) -> g_aggB.
// MODE 2 (layer3): as/adC -> out acc/s + b3 -> outO.
// ---------------------------------------------------------------------------
template<int FOUT, int MODE>
__global__ __launch_bounds__(256)
void gat_gather(int n, const float* __restrict__ bias, float* __restrict__ outO) {
    constexpr int GSZ = FOUT / 4;      // lanes per group
    constexpr int NG  = 32 / GSZ;      // edges per iteration
    int wg = (blockIdx.x * blockDim.x + threadIdx.x) >> 5;
    int lane = threadIdx.x & 31;
    if (wg >= n) return;
    int d = wg;
    int beg = g_off[d], end = g_off[d + 1];
    const float* asv = (MODE == 0) ? g_asA : (MODE == 1 ? g_asB : g_asC);
    float ad = (MODE == 0) ? g_adA[d] : (MODE == 1 ? g_adB[d] : g_adC[d]);
    int g = lane / GSZ, fl = lane % GSZ;

    float4 acc = make_float4(0.f, 0.f, 0.f, 0.f);
    float s = 0.f;

    for (int p0 = beg; p0 < end; p0 += 32) {
        int cnt = min(32, end - p0);
        int src_l = 0;
        float w_l = 0.f;
        if (lane < cnt) {
            src_l = g_csr_src[p0 + lane];
            float v = asv[src_l] + ad;
            v = v > 0.f ? v : NEG_SLOPE * v;
            w_l = __expf(v);
        }
        #pragma unroll 2
        for (int q = 0; q < cnt; q += NG) {
            int idx = q + g;
            float wh  = __shfl_sync(0xffffffffu, w_l, idx & 31);
            int  srch = __shfl_sync(0xffffffffu, src_l, idx & 31);
            float w2 = (idx < cnt) ? wh : 0.f;
            float4 hv = *(const float4*)&g_h[(size_t)srch * FOUT + fl * 4];
            acc.x = fmaf(w2, hv.x, acc.x);
            acc.y = fmaf(w2, hv.y, acc.y);
            acc.z = fmaf(w2, hv.z, acc.z);
            acc.w = fmaf(w2, hv.w, acc.w);
            s += w2;
        }
    }
    // combine groups
    #pragma unroll
    for (int off = GSZ; off < 32; off <<= 1) {
        s     += __shfl_xor_sync(0xffffffffu, s, off);
        acc.x += __shfl_xor_sync(0xffffffffu, acc.x, off);
        acc.y += __shfl_xor_sync(0xffffffffu, acc.y, off);
        acc.z += __shfl_xor_sync(0xffffffffu, acc.z, off);
        acc.w += __shfl_xor_sync(0xffffffffu, acc.w, off);
    }
    float sinv = 1.f / (s + EPS_F);
    if (MODE == 0 && lane == 0) g_sinv[d] = sinv;

    if (lane < GSZ) {
        float4 b = *(const float4*)&bias[fl * 4];
        float4 o;
        if (MODE == 2) {
            o.x = fmaf(acc.x, sinv, b.x);
            o.y = fmaf(acc.y, sinv, b.y);
            o.z = fmaf(acc.z, sinv, b.z);
            o.w = fmaf(acc.w, sinv, b.w);
            *(float4*)&outO[(size_t)d * FOUT + fl * 4] = o;
        } else {
            o.x = fmaxf(fmaf(acc.x, sinv, b.x), 0.f);
            o.y = fmaxf(fmaf(acc.y, sinv, b.y), 0.f);
            o.z = fmaxf(fmaf(acc.z, sinv, b.z), 0.f);
            o.w = fmaxf(fmaf(acc.w, sinv, b.w), 0.f);
            float* outp = (MODE == 0) ? g_aggA : g_aggB;
            *(float4*)&outp[(size_t)d * FOUT + fl * 4] = o;
        }
    }
}

// ---------------------------------------------------------------------------
// Layer-1 alpha, off the critical path: recompute w from the original edge
// list (coalesced writes), alpha = w * sinv[dst]. Reads as/adA + g_sinv only.
// ---------------------------------------------------------------------------
__global__ void alpha_kernel(const int* __restrict__ ei32, int E, int Ep, int n,
                             float* __restrict__ outAlpha) {
    int e = blockIdx.x * blockDim.x + threadIdx.x;
    if (e >= Ep) return;
    int s, d;
    load_edge(ei32, e, E, n, s, d);
    float v = g_asA[s] + g_adA[d];
    v = v > 0.f ? v : NEG_SLOPE * v;
    outAlpha[e] = __expf(v) * g_sinv[d];
}

// ---------------------------------------------------------------------------

extern "C" void kernel_launch(void* const* d_in, const int* in_sizes, int n_in,
                              void* d_out, int out_size) {
    const float* x    = (const float*)d_in[0];
    const int*   ei32 = (const int*)d_in[1];
    const float* W1 = (const float*)d_in[2];
    const float* a1s = (const float*)d_in[3];
    const float* a1d = (const float*)d_in[4];
    const float* b1 = (const float*)d_in[5];
    const float* W2 = (const float*)d_in[6];
    const float* a2s = (const float*)d_in[7];
    const float* a2d = (const float*)d_in[8];
    const float* b2 = (const float*)d_in[9];
    const float* W3 = (const float*)d_in[10];
    const float* a3s = (const float*)d_in[11];
    const float* a3d = (const float*)d_in[12];
    const float* b3 = (const float*)d_in[13];

    const int N  = in_sizes[0] / 128;     // 50000
    const int E  = in_sizes[1] / 2;       // 800000
    const int Ep = E + N;                 // with self loops

    float* out      = (float*)d_out;
    float* outAlpha = out + 2 * (size_t)Ep;
    float* outO     = out + 3 * (size_t)Ep;

    const int TB = 256;
    int ebl = (Ep + TB - 1) / TB;
    int nb = (N + 1023) / 1024;
    int gemm_grid = (N + 15) / 16;
    int gath_grid = (N + 7) / 8;

    // one-time side-stream for off-critical-path work
    static cudaStream_t s2 = nullptr;
    static cudaEvent_t evFork = nullptr, evJoin = nullptr, evG1 = nullptr,
                       evAlpha = nullptr;
    if (!s2) {
        cudaStreamCreateWithFlags(&s2, cudaStreamNonBlocking);
        cudaEventCreateWithFlags(&evFork, cudaEventDisableTiming);
        cudaEventCreateWithFlags(&evJoin, cudaEventDisableTiming);
        cudaEventCreateWithFlags(&evG1, cudaEventDisableTiming);
        cudaEventCreateWithFlags(&evAlpha, cudaEventDisableTiming);
    }

    // fork: GEMM1 on s2, independent of edge preprocessing
    cudaEventRecord(evFork, 0);
    cudaStreamWaitEvent(s2, evFork, 0);
    gat_gemm<128, 64, 0, 0><<<gemm_grid, 128, 0, s2>>>(x, W1, a1s, a1d, N);
    cudaEventRecord(evJoin, s2);

    // preprocessing chain on main stream
    init_kernel<<<(N + TB - 1) / TB, TB>>>(ei32, N);
    build_edges<<<ebl, TB>>>(ei32, E, Ep, N, out);
    scan_single<<<nb, 1024>>>(N, nb);
    place_edges<<<ebl, TB>>>(ei32, E, Ep, N);

    // join: gather1 needs both CSR and GEMM1 results
    cudaStreamWaitEvent(0, evJoin, 0);

    // ---- layer 1: 128 -> 64 ----
    gat_gather<64, 0><<<gath_grid, TB>>>(N, b1, nullptr);
    cudaEventRecord(evG1, 0);

    // alpha output overlaps with layer 2 (reads asA/adA/sinv, all stable)
    cudaStreamWaitEvent(s2, evG1, 0);
    alpha_kernel<<<ebl, TB, 0, s2>>>(ei32, E, Ep, N, outAlpha);
    cudaEventRecord(evAlpha, s2);

    // ---- layer 2: 64 -> 64 ----
    gat_gemm<64, 64, 1, 1><<<gemm_grid, 128>>>(nullptr, W2, a2s, a2d, N);
    gat_gather<64, 1><<<gath_grid, TB>>>(N, b2, nullptr);

    // ---- layer 3: 64 -> 32 ----
    gat_gemm<64, 32, 2, 2><<<gemm_grid, 128>>>(nullptr, W3, a3s, a3d, N);
    gat_gather<32, 2><<<gath_grid, TB>>>(N, b3, outO);

    // rejoin side branch before capture ends
    cudaStreamWaitEvent(0, evAlpha, 0);
}